// round 8
// baseline (speedup 1.0000x reference)
#include <cuda_runtime.h>
#include <cstdint>
#include <cstddef>

#define EPS   1e-6f
#define B_    16
#define NN    1024
#define FDIM  64
#define OUTD  128
#define KC    64
#define NITER (NN / KC)

// smem strides (floats). Conflict-free MMA fragment rules:
//   A-operand stride ≡ 4 (mod 32), B-operand stride ≡ 8 (mod 32)
#define SA_STR 68
#define SB_STR 136
#define OC_STR 196
#define SK_STR 136

// smem layout (float offsets)
#define OFF_ADIAG 0
#define OFF_INV   128
#define OFF_SROW  256
#define OFF_DYN   384
#define ASTG      (128 * SA_STR)          // 8704
#define BSTG      (KC * SB_STR)           // 8704
#define STG       (ASTG + BSTG)           // 17408 per stage
#define OFF_STAGE(s) (OFF_DYN + (s) * STG)
#define OFF_OC    OFF_DYN                           // 128*196 = 25088
#define OFF_KM    (OFF_OC + 128 * OC_STR)           // + 192*136 = 26112
#define SMEM_FLOATS (OFF_DYN + 3 * STG)             // 52608 (covers OC+KM=51968)
#define SMEM_BYTES  (SMEM_FLOATS * 4)               // 210432

__device__ float g_inv[B_ * NN];
__device__ float g_s[B_ * NN];
__device__ float g_B[(size_t)B_ * NN * 128];   // pre-rounded [x | s*x] per batch

__device__ __forceinline__ uint32_t smem_u32(const void* p) {
    uint32_t a;
    asm("{ .reg .u64 t; cvta.to.shared.u64 t, %1; cvt.u32.u64 %0, t; }"
        : "=r"(a) : "l"(p));
    return a;
}
__device__ __forceinline__ void cp_async16(uint32_t saddr, const void* g) {
    asm volatile("cp.async.cg.shared.global [%0], [%1], 16;"
                 :: "r"(saddr), "l"(g) : "memory");
}
#define CP_COMMIT() asm volatile("cp.async.commit_group;" ::: "memory")
#define CP_WAIT1()  asm volatile("cp.async.wait_group 1;" ::: "memory")
#define CP_WAIT0()  asm volatile("cp.async.wait_group 0;" ::: "memory")

__device__ __forceinline__ float to_tf32(float v) {
    float r;
    asm("cvt.rna.tf32.f32 %0, %1;" : "=f"(r) : "f"(v));
    return r;
}
__device__ __forceinline__ uint32_t tf32u(float v) {
    return __float_as_uint(to_tf32(v));
}
__device__ __forceinline__ float4 tf32x4(float4 v) {
    v.x = to_tf32(v.x); v.y = to_tf32(v.y);
    v.z = to_tf32(v.z); v.w = to_tf32(v.w);
    return v;
}
__device__ __forceinline__ void mma_tf32(float* c, const uint32_t* a, const uint32_t* b) {
    asm volatile(
        "mma.sync.aligned.m16n8k8.row.col.f32.tf32.tf32.f32 "
        "{%0,%1,%2,%3}, {%4,%5,%6,%7}, {%8,%9}, {%0,%1,%2,%3};"
        : "+f"(c[0]), "+f"(c[1]), "+f"(c[2]), "+f"(c[3])
        : "r"(a[0]), "r"(a[1]), "r"(a[2]), "r"(a[3]), "r"(b[0]), "r"(b[1]));
}

// ---------------------------------------------------------------------------
// Kernel 1: degree scalars. deg[b,i] = rowsum(A) - A[i,i] + 1
// ---------------------------------------------------------------------------
__global__ void deg_kernel(const float* __restrict__ A) {
    int warp = (blockIdx.x * blockDim.x + threadIdx.x) >> 5;
    int lane = threadIdx.x & 31;
    if (warp >= B_ * NN) return;
    const float* row = A + (size_t)warp * NN;
    float sum = 0.f;
    const float4* r4 = (const float4*)row;
#pragma unroll
    for (int w = 0; w < 8; w++) {
        float4 v = r4[w * 32 + lane];
        sum += v.x + v.y + v.z + v.w;
    }
#pragma unroll
    for (int off = 16; off > 0; off >>= 1)
        sum += __shfl_down_sync(0xFFFFFFFFu, sum, off);
    if (lane == 0) {
        float deg = sum - row[warp % NN] + 1.0f;
        g_inv[warp] = 1.0f / (EPS + deg);
        g_s[warp]   = 1.0f / (EPS + sqrtf(deg));
    }
}

// ---------------------------------------------------------------------------
// Kernel 2: build g_B[b][k][0:64] = tf32(x[k]), [64:128] = tf32(s_k * x[k])
// ---------------------------------------------------------------------------
__global__ void prep_kernel(const float* __restrict__ x) {
    const int b = blockIdx.y;
    int e = blockIdx.x * 512 + threadIdx.x;      // 0..16383 (float4s of x per batch)
    int k = e >> 4, f4 = (e & 15) * 4;
    float4 v = *(const float4*)&x[((size_t)b * NN + k) * FDIM + f4];
    float sv = g_s[b * NN + k];
    float4 w = make_float4(sv * v.x, sv * v.y, sv * v.z, sv * v.w);
    float* dst = &g_B[((size_t)b * NN + k) * 128];
    *(float4*)&dst[f4]      = tf32x4(v);
    *(float4*)&dst[64 + f4] = tf32x4(w);
}

// ---------------------------------------------------------------------------
// Kernel 3: fused. 512 threads, pure cp.async 3-stage pipeline, KC=64.
// A raw (fragment-cvt), B pre-rounded. Diagonal fixed analytically.
// ---------------------------------------------------------------------------
__global__ __launch_bounds__(512, 1)
void fused_mma_kernel(const float* __restrict__ A, const float* __restrict__ x,
                      const float* __restrict__ Kmat, const float* __restrict__ bias,
                      float* __restrict__ out) {
    extern __shared__ float sm[];
    const uint32_t sb = smem_u32(sm);
    const int tid  = threadIdx.x;
    const int wid  = tid >> 5;
    const int lane = tid & 31;
    const int b    = blockIdx.y;
    const int row0 = blockIdx.x * 128;

    const int wm = wid >> 2;          // 0..3 : 32-row band
    const int wn = wid & 3;           // 0..3 : 32-col band of D
    const int m_base = wm * 32;
    const int n_base = wn * 32;
    const int lr = lane >> 2;         // 0..7
    const int lc = lane & 3;          // 0..3
    const bool scaled = (wn >= 2);
    const int f_base = scaled ? (wn - 2) * 32 : n_base;

    const float* Ab = A + (size_t)b * NN * NN;
    const float* xb = x + (size_t)b * NN * FDIM;
    const float* Bb = g_B + (size_t)b * NN * 128;

    // ---- per-row scalars
    if (tid < 128) {
        int grow = row0 + tid;
        sm[OFF_ADIAG + tid] = __ldg(&Ab[(size_t)grow * NN + grow]);
        sm[OFF_INV + tid]   = g_inv[b * NN + grow];
        sm[OFF_SROW + tid]  = g_s[b * NN + grow];
    }

    // ---- cp.async geometry: per stage 2048 A-float4 + 2048 B-float4; 4+4/thread
    const int arow = tid >> 4;                 // 0..31 (A row base, +32q)
    const int acol = (tid & 15) * 4;           // 0..60
    const int bkr  = tid >> 5;                 // 0..15 (B k base, +16q)
    const int bcol = (tid & 31) * 4;           // 0..124
    const float* gA = Ab + (size_t)(row0 + arow) * NN + acol;
    const float* gB = Bb + (size_t)bkr * 128 + bcol;
    uint32_t sA[3], sBs[3];
#pragma unroll
    for (int s = 0; s < 3; s++) {
        sA[s]  = sb + (OFF_STAGE(s) + arow * SA_STR + acol) * 4;
        sBs[s] = sb + (OFF_STAGE(s) + ASTG + bkr * SB_STR + bcol) * 4;
    }

    // ---- prologue: issue stages 0,1
#pragma unroll
    for (int st = 0; st < 2; st++) {
        const int k0 = st * KC;
#pragma unroll
        for (int q = 0; q < 4; q++)
            cp_async16(sA[st] + q * 32 * SA_STR * 4, gA + k0 + (size_t)q * 32 * NN);
#pragma unroll
        for (int q = 0; q < 4; q++)
            cp_async16(sBs[st] + q * 16 * SB_STR * 4, gB + (size_t)(k0 + q * 16) * 128);
        CP_COMMIT();
    }

    float acc[2][4][4];
#pragma unroll
    for (int mt = 0; mt < 2; mt++)
#pragma unroll
        for (int nt = 0; nt < 4; nt++)
#pragma unroll
            for (int q = 0; q < 4; q++) acc[mt][nt][q] = 0.f;

    // ---- mainloop: 16 iters
    for (int it = 0; it < NITER; ++it) {
        if (it + 1 < NITER) { CP_WAIT1(); } else { CP_WAIT0(); }
        __syncthreads();
        if (it + 2 < NITER) {
            const int st = (it + 2) % 3;
            const int k0 = (it + 2) * KC;
#pragma unroll
            for (int q = 0; q < 4; q++)
                cp_async16(sA[st] + q * 32 * SA_STR * 4, gA + k0 + (size_t)q * 32 * NN);
#pragma unroll
            for (int q = 0; q < 4; q++)
                cp_async16(sBs[st] + q * 16 * SB_STR * 4, gB + (size_t)(k0 + q * 16) * 128);
            CP_COMMIT();
        }
        const float* sAt = &sm[OFF_STAGE(it % 3)];
        const float* sBt = sAt + ASTG;
#pragma unroll
        for (int ks = 0; ks < 8; ks++) {
            const int k = ks * 8;
            uint32_t af[2][4], bf[4][2];
#pragma unroll
            for (int mt = 0; mt < 2; mt++) {
                const float* p = sAt + (m_base + mt * 16 + lr) * SA_STR + k + lc;
                af[mt][0] = tf32u(p[0]);
                af[mt][1] = tf32u(p[8 * SA_STR]);
                af[mt][2] = tf32u(p[4]);
                af[mt][3] = tf32u(p[8 * SA_STR + 4]);
            }
#pragma unroll
            for (int nt = 0; nt < 4; nt++) {
                const float* p = sBt + (k + lc) * SB_STR + (scaled ? 64 : 0) +
                                 f_base + nt * 8 + lr;
                bf[nt][0] = __float_as_uint(p[0]);
                bf[nt][1] = __float_as_uint(p[4 * SB_STR]);
            }
#pragma unroll
            for (int mt = 0; mt < 2; mt++)
#pragma unroll
                for (int nt = 0; nt < 4; nt++)
                    mma_tf32(acc[mt][nt], af[mt], bf[nt]);
        }
    }
    __syncthreads();   // pipeline smem dead; safe to overwrite with ocat/Kmat

    // ---- stage Kmat (tf32) into [192][SK_STR]
    {
        const float4* src = (const float4*)Kmat;
#pragma unroll
        for (int i4 = tid; i4 < 192 * 128 / 4; i4 += 512) {
            int row = i4 >> 5, c4 = (i4 & 31) * 4;
            *(float4*)&sm[OFF_KM + row * SK_STR + c4] = tf32x4(src[i4]);
        }
    }

    // ---- epilogue 1: analytic diagonal fix + scalings -> ocat [128][192]
#pragma unroll
    for (int mt = 0; mt < 2; mt++) {
#pragma unroll
        for (int nt = 0; nt < 4; nt++) {
            const int f = f_base + nt * 8 + lc * 2;
#pragma unroll
            for (int h = 0; h < 2; h++) {
                const int r = m_base + mt * 16 + lr + h * 8;
                const float ad = sm[OFF_ADIAG + r];
                const float c0 = acc[mt][nt][h * 2 + 0];
                const float c1 = acc[mt][nt][h * 2 + 1];
                float2 xv = *(const float2*)&xb[(size_t)(row0 + r) * FDIM + f];
                if (!scaled) {
                    const float inv = sm[OFF_INV + r];
                    float o1a = c0 - ad * xv.x;
                    float o1b = c1 - ad * xv.y;
                    float2 w1 = make_float2(to_tf32(o1a), to_tf32(o1b));
                    float2 w2 = make_float2(to_tf32(inv * (o1a + xv.x)),
                                            to_tf32(inv * (o1b + xv.y)));
                    *(float2*)&sm[OFF_OC + r * OC_STR + f]      = w1;
                    *(float2*)&sm[OFF_OC + r * OC_STR + 64 + f] = w2;
                } else {
                    const float sv = sm[OFF_SROW + r];
                    const float t = sv * sv * (1.0f - ad);
                    float2 w3 = make_float2(to_tf32(sv * c0 + t * xv.x),
                                            to_tf32(sv * c1 + t * xv.y));
                    *(float2*)&sm[OFF_OC + r * OC_STR + 128 + f] = w3;
                }
            }
        }
    }
    __syncthreads();

    // ---- GEMM2: out[128,128] = ocat[128,192] @ Kmat[192,128]
#pragma unroll
    for (int mt = 0; mt < 2; mt++)
#pragma unroll
        for (int nt = 0; nt < 4; nt++)
#pragma unroll
            for (int q = 0; q < 4; q++) acc[mt][nt][q] = 0.f;

#pragma unroll
    for (int ks = 0; ks < 24; ks++) {
        const int k = ks * 8;
        uint32_t af[2][4], bf[4][2];
#pragma unroll
        for (int mt = 0; mt < 2; mt++) {
            const float* p = &sm[OFF_OC + (m_base + mt * 16 + lr) * OC_STR + k + lc];
            af[mt][0] = __float_as_uint(p[0]);
            af[mt][1] = __float_as_uint(p[8 * OC_STR]);
            af[mt][2] = __float_as_uint(p[4]);
            af[mt][3] = __float_as_uint(p[8 * OC_STR + 4]);
        }
#pragma unroll
        for (int nt = 0; nt < 4; nt++) {
            const float* p = &sm[OFF_KM + (k + lc) * SK_STR + n_base + nt * 8 + lr];
            bf[nt][0] = __float_as_uint(p[0]);
            bf[nt][1] = __float_as_uint(p[4 * SK_STR]);
        }
#pragma unroll
        for (int mt = 0; mt < 2; mt++)
#pragma unroll
            for (int nt = 0; nt < 4; nt++)
                mma_tf32(acc[mt][nt], af[mt], bf[nt]);
    }

    // ---- bias + relu + store
#pragma unroll
    for (int mt = 0; mt < 2; mt++) {
#pragma unroll
        for (int nt = 0; nt < 4; nt++) {
            const int col = n_base + nt * 8 + lc * 2;
            float2 bv = *(const float2*)&bias[col];
#pragma unroll
            for (int h = 0; h < 2; h++) {
                const int r = m_base + mt * 16 + lr + h * 8;
                float2 o;
                o.x = fmaxf(acc[mt][nt][h * 2 + 0] + bv.x, 0.f);
                o.y = fmaxf(acc[mt][nt][h * 2 + 1] + bv.y, 0.f);
                *(float2*)&out[((size_t)b * NN + row0 + r) * OUTD + col] = o;
            }
        }
    }
}

// ---------------------------------------------------------------------------
extern "C" void kernel_launch(void* const* d_in, const int* in_sizes, int n_in,
                              void* d_out, int out_size) {
    const float *x = nullptr, *A = nullptr, *Kmat = nullptr, *bias = nullptr;
    for (int i = 0; i < n_in; i++) {
        switch (in_sizes[i]) {
            case B_ * NN * FDIM:  x    = (const float*)d_in[i]; break;
            case B_ * NN * NN:    A    = (const float*)d_in[i]; break;
            case 3 * FDIM * OUTD: Kmat = (const float*)d_in[i]; break;
            case OUTD:            bias = (const float*)d_in[i]; break;
        }
    }
    float* out = (float*)d_out;

    static bool attr_set = false;
    if (!attr_set) {
        cudaFuncSetAttribute(fused_mma_kernel,
                             cudaFuncAttributeMaxDynamicSharedMemorySize, SMEM_BYTES);
        attr_set = true;
    }

    deg_kernel<<<(B_ * NN * 32 + 255) / 256, 256>>>(A);
    prep_kernel<<<dim3(32, B_), 512>>>(x);
    fused_mma_kernel<<<dim3(NN / 128, B_), 512, SMEM_BYTES>>>(A, x, Kmat, bias, out);
}

// round 9
// speedup vs baseline: 1.2436x; 1.2436x over previous
#include <cuda_runtime.h>
#include <cstdint>
#include <cstddef>

#define EPS   1e-6f
#define B_    16
#define NN    1024
#define FDIM  64
#define OUTD  128
#define KC    32
#define NITER (NN / KC)

#define SA_STR 36
#define SB_STR 136
#define OC_STR 196
#define SK_STR 136

#define OFF_ADIAG 0
#define OFF_INV   128
#define OFF_SROW  256
#define OFF_DYN   384
#define ASTG      (128 * SA_STR)
#define BSTG      (KC * SB_STR)
#define STG       (ASTG + BSTG)
#define OFF_STAGE(s) (OFF_DYN + (s) * STG)
#define OFF_OC    OFF_DYN
#define OFF_KM    (OFF_DYN + 3 * STG)
#define SMEM_FLOATS (OFF_KM + 192 * SK_STR)
#define SMEM_BYTES  (SMEM_FLOATS * 4)

__device__ float g_inv[B_ * NN];
__device__ float g_s[B_ * NN];
__device__ float g_B[(size_t)B_ * NN * 128];

__device__ __forceinline__ uint32_t smem_u32(const void* p) {
    uint32_t a;
    asm("{ .reg .u64 t; cvta.to.shared.u64 t, %1; cvt.u32.u64 %0, t; }"
        : "=r"(a) : "l"(p));
    return a;
}
__device__ __forceinline__ void cp_async16(uint32_t saddr, const void* g) {
    asm volatile("cp.async.cg.shared.global [%0], [%1], 16;"
                 :: "r"(saddr), "l"(g) : "memory");
}
#define CP_COMMIT() asm volatile("cp.async.commit_group;" ::: "memory")
#define CP_WAIT0()  asm volatile("cp.async.wait_group 0;" ::: "memory")
#define MEMBAR_CTA() asm volatile("membar.cta;" ::: "memory")

__device__ __forceinline__ void bar_sync512(int id) {
    asm volatile("bar.sync %0, 512;" :: "r"(id) : "memory");
}
__device__ __forceinline__ void bar_arrive512(int id) {
    asm volatile("bar.arrive %0, 512;" :: "r"(id) : "memory");
}
__device__ __forceinline__ void bar_sync_n(int id, int n) {
    asm volatile("bar.sync %0, %1;" :: "r"(id), "r"(n) : "memory");
}
__device__ __forceinline__ float to_tf32(float v) {
    float r;
    asm("cvt.rna.tf32.f32 %0, %1;" : "=f"(r) : "f"(v));
    return r;
}
__device__ __forceinline__ float4 tf32x4(float4 v) {
    v.x = to_tf32(v.x); v.y = to_tf32(v.y);
    v.z = to_tf32(v.z); v.w = to_tf32(v.w);
    return v;
}
__device__ __forceinline__ void mma_tf32(float* c, const uint32_t* a, const uint32_t* b) {
    asm volatile(
        "mma.sync.aligned.m16n8k8.row.col.f32.tf32.tf32.f32 "
        "{%0,%1,%2,%3}, {%4,%5,%6,%7}, {%8,%9}, {%0,%1,%2,%3};"
        : "+f"(c[0]), "+f"(c[1]), "+f"(c[2]), "+f"(c[3])
        : "r"(a[0]), "r"(a[1]), "r"(a[2]), "r"(a[3]), "r"(b[0]), "r"(b[1]));
}

__global__ void deg_kernel(const float* __restrict__ A) {
    int warp = (blockIdx.x * blockDim.x + threadIdx.x) >> 5;
    int lane = threadIdx.x & 31;
    if (warp >= B_ * NN) return;
    const float* row = A + (size_t)warp * NN;
    float sum = 0.f;
    const float4* r4 = (const float4*)row;
#pragma unroll
    for (int w = 0; w < 8; w++) {
        float4 v = r4[w * 32 + lane];
        sum += v.x + v.y + v.z + v.w;
    }
#pragma unroll
    for (int off = 16; off > 0; off >>= 1)
        sum += __shfl_down_sync(0xFFFFFFFFu, sum, off);
    if (lane == 0) {
        float deg = sum - row[warp % NN] + 1.0f;
        g_inv[warp] = 1.0f / (EPS + deg);
        g_s[warp]   = 1.0f / (EPS + sqrtf(deg));
    }
}

__global__ void prep_kernel(const float* __restrict__ x) {
    const int b = blockIdx.y;
    int e = blockIdx.x * 512 + threadIdx.x;
    int k = e >> 4, f4 = (e & 15) * 4;
    float4 v = *(const float4*)&x[((size_t)b * NN + k) * FDIM + f4];
    float sv = g_s[b * NN + k];
    float4 w = make_float4(sv * v.x, sv * v.y, sv * v.z, sv * v.w);
    float* dst = &g_B[((size_t)b * NN + k) * 128];
    *(float4*)&dst[f4]      = tf32x4(v);
    *(float4*)&dst[64 + f4] = tf32x4(w);
}

__global__ __launch_bounds__(512, 1)
void fused_mma_kernel(const float* __restrict__ A, const float* __restrict__ x,
                      const float* __restrict__ Kmat, const float* __restrict__ bias,
                      float* __restrict__ out) {
    extern __shared__ float sm[];
    const uint32_t sb = smem_u32(sm);
    const int tid  = threadIdx.x;
    const int wid  = tid >> 5;
    const int lane = tid & 31;
    const int b    = blockIdx.y;
    const int row0 = blockIdx.x * 128;
    const int lr = lane >> 2;
    const int lc = lane & 3;

    const float* Ab = A + (size_t)b * NN * NN;
    const float* xb = x + (size_t)b * NN * FDIM;
    const float* Bb = g_B + (size_t)b * NN * 128;

    if (wid >= 8) {
        // ---------------- PRODUCER ----------------
        const int ptid = tid - 256;
        const int arow = ptid >> 3;
        const int acol = (ptid & 7) * 4;
        const int bkr  = ptid >> 5;
        const int bcol = (ptid & 31) * 4;
        const float* gA = Ab + (size_t)(row0 + arow) * NN + acol;

        if (ptid < 128) {
            int grow = row0 + ptid;
            sm[OFF_ADIAG + ptid] = __ldg(&Ab[(size_t)grow * NN + grow]);
            sm[OFF_INV + ptid]   = g_inv[b * NN + grow];
            sm[OFF_SROW + ptid]  = g_s[b * NN + grow];
        }

        for (int it = 0; it < NITER; ++it) {
            const int s = it % 3;
            const int k0 = it * KC;
            if (it >= 3) bar_sync512(4 + s);
            float4 va[4];
#pragma unroll
            for (int q = 0; q < 4; q++)
                va[q] = *(const float4*)(gA + k0 + (size_t)q * 32 * NN);
            uint32_t sBb = sb + (OFF_STAGE(s) + ASTG) * 4;
#pragma unroll
            for (int q = 0; q < 4; q++)
                cp_async16(sBb + ((bkr + 8 * q) * SB_STR + bcol) * 4,
                           Bb + (size_t)(k0 + bkr + 8 * q) * 128 + bcol);
            CP_COMMIT();
            float* dA = &sm[OFF_STAGE(s)];
#pragma unroll
            for (int q = 0; q < 4; q++)
                *(float4*)&dA[(arow + 32 * q) * SA_STR + acol] = tf32x4(va[q]);
            CP_WAIT0();
            MEMBAR_CTA();
            bar_arrive512(1 + s);
        }
        {
            const float4* src = (const float4*)Kmat;
#pragma unroll
            for (int i4 = ptid; i4 < 192 * 128 / 4; i4 += 256) {
                int row = i4 >> 5, c4 = (i4 & 31) * 4;
                *(float4*)&sm[OFF_KM + row * SK_STR + c4] = tf32x4(src[i4]);
            }
        }
    } else {
        // ---------------- CONSUMER ----------------
        const int m_base = (wid >> 2) * 64;
        const int n_base = (wid & 3) * 32;
        const bool scaled = (n_base >= 64);
        const int f_base = scaled ? n_base - 64 : n_base;

        float acc[4][4][4];
#pragma unroll
        for (int mt = 0; mt < 4; mt++)
#pragma unroll
            for (int nt = 0; nt < 4; nt++)
#pragma unroll
                for (int q = 0; q < 4; q++) acc[mt][nt][q] = 0.f;

        for (int it = 0; it < NITER; ++it) {
            const int s = it % 3;
            bar_sync512(1 + s);
            const float* sA = &sm[OFF_STAGE(s)];
            const float* sB = sA + ASTG;
#pragma unroll
            for (int ks = 0; ks < 4; ks++) {
                const int k = ks * 8;
                uint32_t af[4][4], bf[4][2];
#pragma unroll
                for (int mt = 0; mt < 4; mt++) {
                    const float* p = sA + (m_base + mt * 16 + lr) * SA_STR + k + lc;
                    af[mt][0] = __float_as_uint(p[0]);
                    af[mt][1] = __float_as_uint(p[8 * SA_STR]);
                    af[mt][2] = __float_as_uint(p[4]);
                    af[mt][3] = __float_as_uint(p[8 * SA_STR + 4]);
                }
#pragma unroll
                for (int nt = 0; nt < 4; nt++) {
                    const float* p = sB + (k + lc) * SB_STR + n_base + nt * 8 + lr;
                    bf[nt][0] = __float_as_uint(p[0]);
                    bf[nt][1] = __float_as_uint(p[4 * SB_STR]);
                }
#pragma unroll
                for (int mt = 0; mt < 4; mt++)
#pragma unroll
                    for (int nt = 0; nt < 4; nt++)
                        mma_tf32(acc[mt][nt], af[mt], bf[nt]);
            }
            bar_arrive512(4 + s);
        }
        bar_sync_n(7, 256);

#pragma unroll
        for (int mt = 0; mt < 4; mt++) {
#pragma unroll
            for (int nt = 0; nt < 4; nt++) {
                const int f = f_base + nt * 8 + lc * 2;
#pragma unroll
                for (int h = 0; h < 2; h++) {
                    const int r = m_base + mt * 16 + lr + h * 8;
                    const float ad = sm[OFF_ADIAG + r];
                    const float c0 = acc[mt][nt][h * 2 + 0];
                    const float c1 = acc[mt][nt][h * 2 + 1];
                    float2 xv = *(const float2*)&xb[(size_t)(row0 + r) * FDIM + f];
                    if (!scaled) {
                        const float inv = sm[OFF_INV + r];
                        float o1a = c0 - ad * xv.x;
                        float o1b = c1 - ad * xv.y;
                        float2 w1 = make_float2(to_tf32(o1a), to_tf32(o1b));
                        float2 w2 = make_float2(to_tf32(inv * (o1a + xv.x)),
                                                to_tf32(inv * (o1b + xv.y)));
                        *(float2*)&sm[OFF_OC + r * OC_STR + f]      = w1;
                        *(float2*)&sm[OFF_OC + r * OC_STR + 64 + f] = w2;
                    } else {
                        const float sv = sm[OFF_SROW + r];
                        const float t = sv * sv * (1.0f - ad);
                        float2 w3 = make_float2(to_tf32(sv * c0 + t * xv.x),
                                                to_tf32(sv * c1 + t * xv.y));
                        *(float2*)&sm[OFF_OC + r * OC_STR + 128 + f] = w3;
                    }
                }
            }
        }
    }
    __syncthreads();

    const int m4 = (wid >> 2 & 3) * 32 + (wid >> 4) * 0 + ((wid & 15) >> 2) * 0;
    // simple: 16 warps -> m4 = (wid>>2)*32 (0..96), n4 = (wid&3)*32
    const int mm = (wid >> 2) * 32;
    const int n4 = (wid & 3) * 32;
    (void)m4;
    float acc2[2][4][4];
#pragma unroll
    for (int mt = 0; mt < 2; mt++)
#pragma unroll
        for (int nt = 0; nt < 4; nt++)
#pragma unroll
            for (int q = 0; q < 4; q++) acc2[mt][nt][q] = 0.f;

#pragma unroll
    for (int ks = 0; ks < 24; ks++) {
        const int k = ks * 8;
        uint32_t af[2][4], bf[4][2];
#pragma unroll
        for (int mt = 0; mt < 2; mt++) {
            const float* p = &sm[OFF_OC + (mm + mt * 16 + lr) * OC_STR + k + lc];
            af[mt][0] = __float_as_uint(p[0]);
            af[mt][1] = __float_as_uint(p[8 * OC_STR]);
            af[mt][2] = __float_as_uint(p[4]);
            af[mt][3] = __float_as_uint(p[8 * OC_STR + 4]);
        }
#pragma unroll
        for (int nt = 0; nt < 4; nt++) {
            const float* p = &sm[OFF_KM + (k + lc) * SK_STR + n4 + nt * 8 + lr];
            bf[nt][0] = __float_as_uint(p[0]);
            bf[nt][1] = __float_as_uint(p[4 * SK_STR]);
        }
#pragma unroll
        for (int mt = 0; mt < 2; mt++)
#pragma unroll
            for (int nt = 0; nt < 4; nt++)
                mma_tf32(acc2[mt][nt], af[mt], bf[nt]);
    }

#pragma unroll
    for (int mt = 0; mt < 2; mt++) {
#pragma unroll
        for (int nt = 0; nt < 4; nt++) {
            const int col = n4 + nt * 8 + lc * 2;
            float2 bv = *(const float2*)&bias[col];
#pragma unroll
            for (int h = 0; h < 2; h++) {
                const int r = mm + mt * 16 + lr + h * 8;
                float2 o;
                o.x = fmaxf(acc2[mt][nt][h * 2 + 0] + bv.x, 0.f);
                o.y = fmaxf(acc2[mt][nt][h * 2 + 1] + bv.y, 0.f);
                *(float2*)&out[((size_t)b * NN + row0 + r) * OUTD + col] = o;
            }
        }
    }
}

extern "C" void kernel_launch(void* const* d_in, const int* in_sizes, int n_in,
                              void* d_out, int out_size) {
    const float *x = nullptr, *A = nullptr, *Kmat = nullptr, *bias = nullptr;
    for (int i = 0; i < n_in; i++) {
        switch (in_sizes[i]) {
            case B_ * NN * FDIM:  x    = (const float*)d_in[i]; break;
            case B_ * NN * NN:    A    = (const float*)d_in[i]; break;
            case 3 * FDIM * OUTD: Kmat = (const float*)d_in[i]; break;
            case OUTD:            bias = (const float*)d_in[i]; break;
        }
    }
    float* out = (float*)d_out;

    static bool attr_set = false;
    if (!attr_set) {
        cudaFuncSetAttribute(fused_mma_kernel,
                             cudaFuncAttributeMaxDynamicSharedMemorySize, SMEM_BYTES);
        attr_set = true;
    }

    deg_kernel<<<(B_ * NN * 32 + 255) / 256, 256>>>(A);
    prep_kernel<<<dim3(32, B_), 512>>>(x);
    fused_mma_kernel<<<dim3(NN / 128, B_), 512, SMEM_BYTES>>>(A, x, Kmat, bias, out);
}